// round 10
// baseline (speedup 1.0000x reference)
#include <cuda_runtime.h>
#include <cuda_bf16.h>
#include <cstdint>

namespace {
constexpr int NTOK = 256;
constexpr int DIM  = 1024;
constexpr int NBLK = 192;   // co-resident: 192 <= 148 SMs * 2 blocks
}

// ---------------- scratch (static device globals, graph/alloc-safe) --------
__device__ float g_part[24][NTOK * NTOK];     // split-k partials: z = m*8 + s
__device__ __nv_bfloat16 g_bf[4][NTOK * DIM]; // 0:hi1 1:lo1 2:hi2 3:lo2
__device__ double g_loss;                      // reset by block 0 each run
__device__ unsigned long long g_pairs;         // idem
__device__ int g_selIsByte;
__device__ unsigned g_bar[3];                  // generation barriers, never reset

// ---------------- helpers ---------------------------------------------------
__device__ __forceinline__ uint32_t smem_u32(const void* p) {
    uint32_t a;
    asm("{ .reg .u64 t; cvta.to.shared.u64 t, %1; cvt.u32.u64 %0, t; }" : "=r"(a) : "l"(p));
    return a;
}
__device__ __forceinline__ void ldsm4(uint32_t* r, uint32_t addr) {
    asm volatile("ldmatrix.sync.aligned.m8n8.x4.shared.b16 {%0,%1,%2,%3}, [%4];"
                 : "=r"(r[0]), "=r"(r[1]), "=r"(r[2]), "=r"(r[3]) : "r"(addr));
}
__device__ __forceinline__ void mma_bf16(float* c, const uint32_t* a, const uint32_t* b) {
    asm volatile("mma.sync.aligned.m16n8k16.row.col.f32.bf16.bf16.f32 "
                 "{%0,%1,%2,%3}, {%4,%5,%6,%7}, {%8,%9}, {%0,%1,%2,%3};"
                 : "+f"(c[0]), "+f"(c[1]), "+f"(c[2]), "+f"(c[3])
                 : "r"(a[0]), "r"(a[1]), "r"(a[2]), "r"(a[3]), "r"(b[0]), "r"(b[1]));
}

// Generation-based grid barrier: counter is monotonic (no reset), so it is
// correct across the correctness call, capture, and every graph replay.
// Safe because all NBLK blocks are guaranteed co-resident (see launch bounds).
__device__ __forceinline__ void grid_barrier(int k) {
    __syncthreads();
    if (threadIdx.x == 0) {
        __threadfence();
        const unsigned arr = atomicAdd(&g_bar[k], 1u);
        const unsigned gen = arr / NBLK;
        while ((*(volatile unsigned*)&g_bar[k]) / NBLK == gen) __nanosleep(64);
        __threadfence();
    }
    __syncthreads();
}

// ---------------------------------------------------------------------------
// Loss inner loop: compacted pos/neg, sentinel-padded to multiples of 32;
// templated NB keeps neg values register-resident; two interleaved product
// chains; one __logf per 32 pairs.
//   softplus(n-p) = max(n-p,0) + log(1 + exp(-|n-p|))
// ---------------------------------------------------------------------------
template <int NB>
__device__ __forceinline__ float row_loss(const float* __restrict__ sPos,
                                          const float* __restrict__ sNeg,
                                          int Ppad, int kl, int jg) {
    float nr[NB];
#pragma unroll
    for (int u = 0; u < NB; u++) nr[u] = sNeg[kl + u * 32];
    float relu = 0.f, lacc = 0.f;
    for (int j = jg; j < Ppad; j += 8) {
        const float p = sPos[j];
        float prodA = 1.f, prodB = 1.f;
#pragma unroll
        for (int u = 0; u < NB; u++) {
            const float x = nr[u] - p;
            relu += fmaxf(x, 0.f);
            const float e = __expf(-fabsf(x));
            if (u & 1) prodB = __fmaf_rn(prodB, e, prodB);
            else       prodA = __fmaf_rn(prodA, e, prodA);
        }
        lacc += __logf(prodA) + __logf(prodB);
    }
    return relu + lacc;
}

// ---------------------------------------------------------------------------
// Fused persistent kernel: convert -> barrier -> gemm -> barrier -> loss ->
// barrier -> finalize. One launch, no inter-kernel ramps/tails.
// Shared memory: raw 55296B region, phase-aliased.
//   GEMM:  Ah @ 0 (18432) | Al @ 18432 | Bh @ 36864 (9216) | Bl @ 46080
//   LOSS:  pos @ 0 (1024) | neg @ 1024 | wPos @ 2048 (32) | red @ 2080 (32)
// ---------------------------------------------------------------------------
__global__ __launch_bounds__(256, 2) void fused_kernel(const float* __restrict__ f1,
                                                       const float* __restrict__ f2,
                                                       const int* __restrict__ mc,
                                                       const int* __restrict__ m1,
                                                       const int* __restrict__ m2,
                                                       const unsigned char* __restrict__ s1,
                                                       const unsigned char* __restrict__ s2,
                                                       float* __restrict__ out) {
    __shared__ __align__(16) unsigned char shraw[55296];
    const int tid = threadIdx.x;
    const int lane = tid & 31;
    const int wid = tid >> 5;
    const int bid = blockIdx.x;

    // ======================= Phase A: convert + sniff =======================
    if (bid == 0) {
        // mask_sents dtype sniff: int32 {0,1} has all non-word-aligned bytes 0
        int v = 0;
        if ((tid & 3) != 0) v = (int)s1[tid] | (int)s2[tid];
        const int any = __syncthreads_or(v);
        if (tid == 0) g_selIsByte = (any != 0) ? 1 : 0;
    }
    for (int idx = bid * 256 + tid; idx < 131072; idx += NBLK * 256) {
        const int sel = idx >> 16;              // 0: f1, 1: f2
        const int off = (idx & 65535) * 4;
        const float4 v = *(const float4*)&((sel ? f2 : f1)[off]);
        __nv_bfloat16 h0 = __float2bfloat16_rn(v.x);
        __nv_bfloat16 h1 = __float2bfloat16_rn(v.y);
        __nv_bfloat16 h2 = __float2bfloat16_rn(v.z);
        __nv_bfloat16 h3 = __float2bfloat16_rn(v.w);
        __nv_bfloat162 hA(h0, h1), hB(h2, h3);
        __nv_bfloat162 lA(__float2bfloat16_rn(v.x - __bfloat162float(h0)),
                          __float2bfloat16_rn(v.y - __bfloat162float(h1)));
        __nv_bfloat162 lB(__float2bfloat16_rn(v.z - __bfloat162float(h2)),
                          __float2bfloat16_rn(v.w - __bfloat162float(h3)));
        *(uint2*)&g_bf[sel * 2][off]     = make_uint2(*(uint32_t*)&hA, *(uint32_t*)&hB);
        *(uint2*)&g_bf[sel * 2 + 1][off] = make_uint2(*(uint32_t*)&lA, *(uint32_t*)&lB);
    }
    grid_barrier(0);

    // ======================= Phase B: tensor GEMM ==========================
    // Block tile 128x64, k-split 128. bid = ((m*8)+s)*8 + rt*4 + ct.
    {
        __nv_bfloat16* sAh = (__nv_bfloat16*)(shraw);
        __nv_bfloat16* sAl = (__nv_bfloat16*)(shraw + 18432);
        __nv_bfloat16* sBh = (__nv_bfloat16*)(shraw + 36864);
        __nv_bfloat16* sBl = (__nv_bfloat16*)(shraw + 46080);

        const int tile = bid & 7;
        const int rt = tile >> 2;
        const int ct = tile & 3;
        const int zz = bid >> 3;
        const int m = zz >> 3;
        const int s = zz & 7;
        const int rbase = rt * 128;
        const int cbase = ct * 64;
        const int k0 = s * 128;

        const __nv_bfloat16* __restrict__ Ah = g_bf[(m == 2) ? 2 : 0];
        const __nv_bfloat16* __restrict__ Al = g_bf[(m == 2) ? 3 : 1];
        const __nv_bfloat16* __restrict__ Bh = g_bf[(m == 1) ? 0 : 2];
        const __nv_bfloat16* __restrict__ Bl = g_bf[(m == 1) ? 1 : 3];

        const uint32_t uAh = smem_u32(sAh);
        const uint32_t uAl = smem_u32(sAl);
        const uint32_t uBh = smem_u32(sBh);
        const uint32_t uBl = smem_u32(sBl);

        const int wr = wid >> 1;
        const int wc = wid & 1;
        const int arow = lane & 15;
        const int acol = (lane >> 4) << 3;
        const uint32_t aoff = (uint32_t)(((wr * 32 + arow) * 72 + acol) * 2);
        const int bi = lane & 7;
        const int bq = lane >> 3;
        const uint32_t boff = (uint32_t)(((wc * 32 + ((bq >> 1) << 3) + bi) * 72 + ((bq & 1) << 3)) * 2);

        float C[2][4][4];
#pragma unroll
        for (int mt = 0; mt < 2; mt++)
#pragma unroll
            for (int nt = 0; nt < 4; nt++)
#pragma unroll
                for (int q = 0; q < 4; q++) C[mt][nt][q] = 0.f;

#pragma unroll
        for (int chunk = 0; chunk < 2; chunk++) {
            const int kg = k0 + chunk * 64;
            __syncthreads();
#pragma unroll
            for (int it = 0; it < 4; it++) {
                const int v = tid + it * 256;
                const int r = v >> 3;
                const int q = v & 7;
                const int g = (rbase + r) * DIM + kg + q * 8;
                const int o = r * 72 + q * 8;
                *(uint4*)&sAh[o] = *(const uint4*)&Ah[g];
                *(uint4*)&sAl[o] = *(const uint4*)&Al[g];
            }
#pragma unroll
            for (int it = 0; it < 2; it++) {
                const int v = tid + it * 256;
                const int r = v >> 3;
                const int q = v & 7;
                const int g = (cbase + r) * DIM + kg + q * 8;
                const int o = r * 72 + q * 8;
                *(uint4*)&sBh[o] = *(const uint4*)&Bh[g];
                *(uint4*)&sBl[o] = *(const uint4*)&Bl[g];
            }
            __syncthreads();

#pragma unroll
            for (int kk = 0; kk < 4; kk++) {
                const uint32_t ka = aoff + kk * 32;
                const uint32_t kb = boff + kk * 32;
                uint32_t ah[2][4], al[2][4], bh[8], bl[8];
                ldsm4(ah[0], uAh + ka);
                ldsm4(ah[1], uAh + ka + 16 * 72 * 2);
                ldsm4(al[0], uAl + ka);
                ldsm4(al[1], uAl + ka + 16 * 72 * 2);
                ldsm4(bh,     uBh + kb);
                ldsm4(bh + 4, uBh + kb + 16 * 72 * 2);
                ldsm4(bl,     uBl + kb);
                ldsm4(bl + 4, uBl + kb + 16 * 72 * 2);
#pragma unroll
                for (int mt = 0; mt < 2; mt++)
#pragma unroll
                    for (int nt = 0; nt < 4; nt++) {
                        mma_bf16(C[mt][nt], ah[mt], &bh[nt * 2]);
                        mma_bf16(C[mt][nt], ah[mt], &bl[nt * 2]);
                        mma_bf16(C[mt][nt], al[mt], &bh[nt * 2]);
                    }
            }
        }

        float* __restrict__ dst = g_part[m * 8 + s];
        const int erow = lane >> 2;
        const int ecol = (lane & 3) * 2;
#pragma unroll
        for (int mt = 0; mt < 2; mt++)
#pragma unroll
            for (int nt = 0; nt < 4; nt++) {
                const int r0 = rbase + wr * 32 + mt * 16 + erow;
                const int cc = cbase + wc * 32 + nt * 8 + ecol;
                *(float2*)&dst[r0 * NTOK + cc] = make_float2(C[mt][nt][0], C[mt][nt][1]);
                *(float2*)&dst[(r0 + 8) * NTOK + cc] = make_float2(C[mt][nt][2], C[mt][nt][3]);
            }
    }
    grid_barrier(1);

    // ======================= Phase C: loss =================================
    {
        float* sPos = (float*)(shraw);
        float* sNeg = (float*)(shraw + 1024);
        int*   wPos = (int*)(shraw + 2048);
        float* sRed = (float*)(shraw + 2080);

        const int selIsByte = g_selIsByte;
        double lsum = 0.0;                       // tid 0 only
        unsigned long long psum = 0ull;          // tid 0 only

        for (int task = bid; task < 1024; task += NBLK) {
            const int t = task >> 8;
            const int i = task & 255;

            const void* selP = (t == 0 || t == 2) ? (const void*)s1 : (const void*)s2;
            int sel;
            if (selIsByte) sel = ((const unsigned char*)selP)[i];
            else           sel = ((const int*)selP)[i];
            if (!sel) continue;                  // uniform across block

            // fused split-k reduce while loading
            const int mIdx = (t <= 1) ? 0 : (t - 1);
            const int off = (t == 1) ? (tid * 256 + i) : (i * 256 + tid);
            const float* __restrict__ pb = g_part[mIdx * 8];
            float v = 0.f;
#pragma unroll
            for (int sp = 0; sp < 8; sp++) v += pb[sp * 65536 + off];

            int mk;
            if (t == 0)      mk = mc[i * 256 + tid];
            else if (t == 1) mk = mc[tid * 256 + i];
            else if (t == 2) mk = m1[i * 256 + tid];
            else             mk = m2[i * 256 + tid];

            const unsigned bp = __ballot_sync(0xffffffffu, mk != 0);
            if (lane == 0) wPos[wid] = __popc(bp);
            __syncthreads();

            int baseP = 0, P = 0;
#pragma unroll
            for (int w = 0; w < 8; w++) {
                const int c = wPos[w];
                if (w < wid) baseP += c;
                P += c;
            }
            const int N = 256 - P;
            const int baseN = wid * 32 - baseP;
            const unsigned lt = (1u << lane) - 1u;
            if (mk) sPos[baseP + __popc(bp & lt)] = v;
            else    sNeg[baseN + __popc(~bp & lt)] = v;
            __syncthreads();

            if (tid == 0) psum += (unsigned long long)P * (unsigned long long)N;
            if (P == 0 || N == 0) { __syncthreads(); continue; }

            const int Ppad = (P + 31) & ~31;
            const int Npad = (N + 31) & ~31;
            if (tid >= P && tid < Ppad) sPos[tid] = 1e30f;
            if (tid >= N && tid < Npad) sNeg[tid] = -1e30f;
            __syncthreads();

            const int kl = tid & 31;
            const int jg = tid >> 5;
            float total;
            switch (Npad >> 5) {
                case 1: total = row_loss<1>(sPos, sNeg, Ppad, kl, jg); break;
                case 2: total = row_loss<2>(sPos, sNeg, Ppad, kl, jg); break;
                case 3: total = row_loss<3>(sPos, sNeg, Ppad, kl, jg); break;
                case 4: total = row_loss<4>(sPos, sNeg, Ppad, kl, jg); break;
                case 5: total = row_loss<5>(sPos, sNeg, Ppad, kl, jg); break;
                case 6: total = row_loss<6>(sPos, sNeg, Ppad, kl, jg); break;
                case 7: total = row_loss<7>(sPos, sNeg, Ppad, kl, jg); break;
                default: total = row_loss<8>(sPos, sNeg, Ppad, kl, jg); break;
            }

#pragma unroll
            for (int o = 16; o; o >>= 1) total += __shfl_xor_sync(0xffffffffu, total, o);
            if (lane == 0) sRed[wid] = total;
            __syncthreads();
            if (tid == 0) {
                float bs = 0.f;
#pragma unroll
                for (int w = 0; w < 8; w++) bs += sRed[w];
                lsum += (double)bs;
            }
            __syncthreads();
        }

        if (tid == 0) {
            if (psum) atomicAdd(&g_pairs, psum);
            if (lsum != 0.0) atomicAdd(&g_loss, lsum);
        }
    }
    grid_barrier(2);

    // ======================= finalize (block 0) ============================
    if (bid == 0 && tid == 0) {
        const unsigned long long p = g_pairs;
        const double l = g_loss;
        out[0] = (float)((p > 0ull) ? (l / (double)p) : l);
        g_loss = 0.0;          // reset for next replay (no one reads until
        g_pairs = 0ull;        // after barrier 1 of the NEXT launch)
        __threadfence();
    }
}

// ---------------------------------------------------------------------------
// Inputs: 0 f1 f32[256,1024]  1 f2 f32[256,1024]  2 mask_cross i32[256,256]
//         3 mask1 i32[256,256] 4 mask2 i32[256,256] 5/6 mask_sents bool[256]
// ---------------------------------------------------------------------------
extern "C" void kernel_launch(void* const* d_in, const int* in_sizes, int n_in,
                              void* d_out, int out_size) {
    const float* f1 = (const float*)d_in[0];
    const float* f2 = (const float*)d_in[1];
    const int* mc = (const int*)d_in[2];
    const int* m1 = (const int*)d_in[3];
    const int* m2 = (const int*)d_in[4];
    const unsigned char* s1 = (const unsigned char*)d_in[5];
    const unsigned char* s2 = (const unsigned char*)d_in[6];

    fused_kernel<<<NBLK, 256>>>(f1, f2, mc, m1, m2, s1, s2, (float*)d_out);
}

// round 12
// speedup vs baseline: 1.3148x; 1.3148x over previous
#include <cuda_runtime.h>
#include <cuda_bf16.h>
#include <cstdint>

namespace {
constexpr int NTOK = 256;
constexpr int DIM  = 1024;
}

// ---------------- scratch (static device globals, graph/alloc-safe) --------
__device__ float g_part[24][NTOK * NTOK];     // split-k partials: z = m*8 + s
__device__ double g_loss;                      // zero-init; reset by last loss block
__device__ unsigned long long g_pairs;         // idem
__device__ unsigned g_count;                   // idem
__device__ int g_selIsByte;

// ---------------- helpers ---------------------------------------------------
__device__ __forceinline__ uint32_t smem_u32(const void* p) {
    uint32_t a;
    asm("{ .reg .u64 t; cvta.to.shared.u64 t, %1; cvt.u32.u64 %0, t; }" : "=r"(a) : "l"(p));
    return a;
}
__device__ __forceinline__ void ldsm4(uint32_t* r, uint32_t addr) {
    asm volatile("ldmatrix.sync.aligned.m8n8.x4.shared.b16 {%0,%1,%2,%3}, [%4];"
                 : "=r"(r[0]), "=r"(r[1]), "=r"(r[2]), "=r"(r[3]) : "r"(addr));
}
__device__ __forceinline__ void mma_bf16(float* c, const uint32_t* a, const uint32_t* b) {
    asm volatile("mma.sync.aligned.m16n8k16.row.col.f32.bf16.bf16.f32 "
                 "{%0,%1,%2,%3}, {%4,%5,%6,%7}, {%8,%9}, {%0,%1,%2,%3};"
                 : "+f"(c[0]), "+f"(c[1]), "+f"(c[2]), "+f"(c[3])
                 : "r"(a[0]), "r"(a[1]), "r"(a[2]), "r"(a[3]), "r"(b[0]), "r"(b[1]));
}
// float4 -> packed hi bf16x4 (uint2) and lo bf16x4 (uint2)
__device__ __forceinline__ void split4(const float4 v, uint2& hi, uint2& lo) {
    __nv_bfloat16 h0 = __float2bfloat16_rn(v.x);
    __nv_bfloat16 h1 = __float2bfloat16_rn(v.y);
    __nv_bfloat16 h2 = __float2bfloat16_rn(v.z);
    __nv_bfloat16 h3 = __float2bfloat16_rn(v.w);
    __nv_bfloat162 hA(h0, h1), hB(h2, h3);
    __nv_bfloat162 lA(__float2bfloat16_rn(v.x - __bfloat162float(h0)),
                      __float2bfloat16_rn(v.y - __bfloat162float(h1)));
    __nv_bfloat162 lB(__float2bfloat16_rn(v.z - __bfloat162float(h2)),
                      __float2bfloat16_rn(v.w - __bfloat162float(h3)));
    hi = make_uint2(*(uint32_t*)&hA, *(uint32_t*)&hB);
    lo = make_uint2(*(uint32_t*)&lA, *(uint32_t*)&lB);
}

// ---------------------------------------------------------------------------
// Tensor GEMM with fused fp32 -> bf16 hi/lo conversion in the staging path
// (mma.sync, plain compute_103-safe; tcgen05 is rejected by this harness's
// ptxas target). Block tile 128 rows x 64 cols over one 128-wide k-split.
// grid 192: bz = ((m*8)+s)*8 + rt*4 + ct. 8 warps as 4x2, warp tile 32x32.
// bf16 split: acc = hiA*hiB + hiA*loB + loA*hiB (error ~1e-6 << 1e-3 tol).
// SMEM stride 72 halves (144B) -> ldmatrix conflict-free. Partials to
// g_part[m*8+s] (exclusive tiles -> deterministic); loss sums the 8 splits.
// Block 0 also sniffs the mask_sents dtype (bool bytes vs int32): int32
// {0,1} has every non-word-aligned byte zero; a random bool vector doesn't.
// ---------------------------------------------------------------------------
__global__ __launch_bounds__(256) void gemm_mma_kernel(const float* __restrict__ f1,
                                                       const float* __restrict__ f2,
                                                       const unsigned char* __restrict__ s1,
                                                       const unsigned char* __restrict__ s2) {
    __shared__ __align__(16) __nv_bfloat16 sAh[128 * 72];
    __shared__ __align__(16) __nv_bfloat16 sAl[128 * 72];
    __shared__ __align__(16) __nv_bfloat16 sBh[64 * 72];
    __shared__ __align__(16) __nv_bfloat16 sBl[64 * 72];

    const int tid = threadIdx.x;
    const int lane = tid & 31;
    const int wid = tid >> 5;

    if (blockIdx.x == 0) {
        int v = 0;
        if ((tid & 3) != 0) v = (int)s1[tid] | (int)s2[tid];
        const int any = __syncthreads_or(v);
        if (tid == 0) g_selIsByte = (any != 0) ? 1 : 0;
    }

    const int bz = blockIdx.x;
    const int tile = bz & 7;
    const int rt = tile >> 2;
    const int ct = tile & 3;
    const int zz = bz >> 3;
    const int m = zz >> 3;
    const int s = zz & 7;
    const int rbase = rt * 128;
    const int cbase = ct * 64;
    const int k0 = s * 128;

    const float* __restrict__ A = (m == 2) ? f2 : f1;
    const float* __restrict__ B = (m == 1) ? f1 : f2;

    const uint32_t uAh = smem_u32(sAh);
    const uint32_t uAl = smem_u32(sAl);
    const uint32_t uBh = smem_u32(sBh);
    const uint32_t uBl = smem_u32(sBl);

    const int wr = wid >> 1;     // 0..3: 32-row group
    const int wc = wid & 1;      // 0..1: 32-col group

    // ldmatrix lane addressing (byte offsets)
    const int arow = lane & 15;
    const int acol = (lane >> 4) << 3;
    const uint32_t aoff = (uint32_t)(((wr * 32 + arow) * 72 + acol) * 2);
    const int bi = lane & 7;
    const int bq = lane >> 3;
    const uint32_t boff = (uint32_t)(((wc * 32 + ((bq >> 1) << 3) + bi) * 72 + ((bq & 1) << 3)) * 2);

    float C[2][4][4];
#pragma unroll
    for (int mt = 0; mt < 2; mt++)
#pragma unroll
        for (int nt = 0; nt < 4; nt++)
#pragma unroll
            for (int q = 0; q < 4; q++) C[mt][nt][q] = 0.f;

#pragma unroll
    for (int chunk = 0; chunk < 2; chunk++) {
        const int kg = k0 + chunk * 64;
        __syncthreads();
        // Stage A: 128 rows x 64 fp32 -> hi/lo bf16. 1024 8-elem groups (4/thread).
#pragma unroll
        for (int it = 0; it < 4; it++) {
            const int v = tid + it * 256;
            const int r = v >> 3;           // 0..127
            const int q = v & 7;            // 8-elem group in row
            const float* gp = &A[(rbase + r) * DIM + kg + q * 8];
            const float4 vx = *(const float4*)gp;
            const float4 vy = *(const float4*)(gp + 4);
            uint2 hx, lx, hy, ly;
            split4(vx, hx, lx);
            split4(vy, hy, ly);
            const int o = r * 72 + q * 8;
            *(uint4*)&sAh[o] = make_uint4(hx.x, hx.y, hy.x, hy.y);
            *(uint4*)&sAl[o] = make_uint4(lx.x, lx.y, ly.x, ly.y);
        }
        // Stage B: 64 rows x 64 fp32 -> hi/lo bf16. 512 groups (2/thread).
#pragma unroll
        for (int it = 0; it < 2; it++) {
            const int v = tid + it * 256;
            const int r = v >> 3;           // 0..63
            const int q = v & 7;
            const float* gp = &B[(cbase + r) * DIM + kg + q * 8];
            const float4 vx = *(const float4*)gp;
            const float4 vy = *(const float4*)(gp + 4);
            uint2 hx, lx, hy, ly;
            split4(vx, hx, lx);
            split4(vy, hy, ly);
            const int o = r * 72 + q * 8;
            *(uint4*)&sBh[o] = make_uint4(hx.x, hx.y, hy.x, hy.y);
            *(uint4*)&sBl[o] = make_uint4(lx.x, lx.y, ly.x, ly.y);
        }
        __syncthreads();

#pragma unroll
        for (int kk = 0; kk < 4; kk++) {
            const uint32_t ka = aoff + kk * 32;   // kk*16 halves
            const uint32_t kb = boff + kk * 32;
            uint32_t ah[2][4], al[2][4], bh[8], bl[8];
            ldsm4(ah[0], uAh + ka);
            ldsm4(ah[1], uAh + ka + 16 * 72 * 2);
            ldsm4(al[0], uAl + ka);
            ldsm4(al[1], uAl + ka + 16 * 72 * 2);
            ldsm4(bh,     uBh + kb);
            ldsm4(bh + 4, uBh + kb + 16 * 72 * 2);
            ldsm4(bl,     uBl + kb);
            ldsm4(bl + 4, uBl + kb + 16 * 72 * 2);
#pragma unroll
            for (int mt = 0; mt < 2; mt++)
#pragma unroll
                for (int nt = 0; nt < 4; nt++) {
                    mma_bf16(C[mt][nt], ah[mt], &bh[nt * 2]);
                    mma_bf16(C[mt][nt], ah[mt], &bl[nt * 2]);
                    mma_bf16(C[mt][nt], al[mt], &bh[nt * 2]);
                }
        }
    }

    // Epilogue: write split-k partials (exclusive tiles -> deterministic)
    float* __restrict__ dst = g_part[m * 8 + s];
    const int erow = lane >> 2;
    const int ecol = (lane & 3) * 2;
#pragma unroll
    for (int mt = 0; mt < 2; mt++)
#pragma unroll
        for (int nt = 0; nt < 4; nt++) {
            const int r0 = rbase + wr * 32 + mt * 16 + erow;
            const int cc = cbase + wc * 32 + nt * 8 + ecol;
            *(float2*)&dst[r0 * NTOK + cc] = make_float2(C[mt][nt][0], C[mt][nt][1]);
            *(float2*)&dst[(r0 + 8) * NTOK + cc] = make_float2(C[mt][nt][2], C[mt][nt][3]);
        }
}

// ---------------------------------------------------------------------------
// Loss (+ fused split-k reduce + fused final): one block per (term, row).
// Each thread sums the 8 L2-resident split-k partials while loading. After
// contributions, the LAST block (threadfence + counter) computes the output
// scalar and resets the accumulators for the next graph replay.
// ---------------------------------------------------------------------------
template <int NB>
__device__ __forceinline__ float row_loss(const float* __restrict__ sPos,
                                          const float* __restrict__ sNeg,
                                          int Ppad, int kl, int jg) {
    float nr[NB];
#pragma unroll
    for (int u = 0; u < NB; u++) nr[u] = sNeg[kl + u * 32];
    float relu = 0.f, lacc = 0.f;
    for (int j = jg; j < Ppad; j += 8) {
        const float p = sPos[j];
        float prodA = 1.f, prodB = 1.f;
#pragma unroll
        for (int u = 0; u < NB; u++) {
            const float x = nr[u] - p;
            relu += fmaxf(x, 0.f);
            const float e = __expf(-fabsf(x));
            if (u & 1) prodB = __fmaf_rn(prodB, e, prodB);
            else       prodA = __fmaf_rn(prodA, e, prodA);
        }
        lacc += __logf(prodA) + __logf(prodB);
    }
    return relu + lacc;
}

__global__ __launch_bounds__(256) void loss_kernel(const int* __restrict__ mc,
                                                   const int* __restrict__ m1,
                                                   const int* __restrict__ m2,
                                                   const void* __restrict__ s1p,
                                                   const void* __restrict__ s2p,
                                                   float* __restrict__ out) {
    const int r = blockIdx.x;
    const int t = r >> 8;
    const int i = r & 255;

    const void* selP = (t == 0 || t == 2) ? s1p : s2p;
    int sel;
    if (g_selIsByte) sel = ((const unsigned char*)selP)[i];
    else             sel = ((const int*)selP)[i];

    __shared__ float sPos[256];
    __shared__ float sNeg[256];
    __shared__ int wPos[8];
    __shared__ float sRed[8];

    const int tid = threadIdx.x;
    const int lane = tid & 31;
    const int wid = tid >> 5;

    if (sel) {  // uniform across block
        const int mIdx = (t <= 1) ? 0 : (t - 1);
        const int off = (t == 1) ? (tid * 256 + i) : (i * 256 + tid);
        const float* __restrict__ pb = g_part[mIdx * 8];
        float v = 0.f;
#pragma unroll
        for (int sp = 0; sp < 8; sp++) v += pb[sp * 65536 + off];

        int mk;
        if (t == 0)      mk = mc[i * 256 + tid];
        else if (t == 1) mk = mc[tid * 256 + i];
        else if (t == 2) mk = m1[i * 256 + tid];
        else             mk = m2[i * 256 + tid];

        const unsigned bp = __ballot_sync(0xffffffffu, mk != 0);
        if (lane == 0) wPos[wid] = __popc(bp);
        __syncthreads();

        int baseP = 0, P = 0;
#pragma unroll
        for (int w = 0; w < 8; w++) {
            const int c = wPos[w];
            if (w < wid) baseP += c;
            P += c;
        }
        const int N = 256 - P;
        const int baseN = wid * 32 - baseP;
        const unsigned lt = (1u << lane) - 1u;
        if (mk) sPos[baseP + __popc(bp & lt)] = v;
        else    sNeg[baseN + __popc(~bp & lt)] = v;
        __syncthreads();

        if (tid == 0)
            atomicAdd(&g_pairs, (unsigned long long)P * (unsigned long long)N);

        if (P != 0 && N != 0) {  // uniform
            const int Ppad = (P + 31) & ~31;
            const int Npad = (N + 31) & ~31;
            if (tid >= P && tid < Ppad) sPos[tid] = 1e30f;
            if (tid >= N && tid < Npad) sNeg[tid] = -1e30f;
            __syncthreads();

            const int kl = tid & 31;
            const int jg = tid >> 5;
            float total;
            switch (Npad >> 5) {
                case 1: total = row_loss<1>(sPos, sNeg, Ppad, kl, jg); break;
                case 2: total = row_loss<2>(sPos, sNeg, Ppad, kl, jg); break;
                case 3: total = row_loss<3>(sPos, sNeg, Ppad, kl, jg); break;
                case 4: total = row_loss<4>(sPos, sNeg, Ppad, kl, jg); break;
                case 5: total = row_loss<5>(sPos, sNeg, Ppad, kl, jg); break;
                case 6: total = row_loss<6>(sPos, sNeg, Ppad, kl, jg); break;
                case 7: total = row_loss<7>(sPos, sNeg, Ppad, kl, jg); break;
                default: total = row_loss<8>(sPos, sNeg, Ppad, kl, jg); break;
            }

#pragma unroll
            for (int o = 16; o; o >>= 1) total += __shfl_xor_sync(0xffffffffu, total, o);
            if (lane == 0) sRed[wid] = total;
            __syncthreads();
            if (tid == 0) {
                float bs = 0.f;
#pragma unroll
                for (int w = 0; w < 8; w++) bs += sRed[w];
                atomicAdd(&g_loss, (double)bs);
            }
        }
    }

    // Completion protocol: every block arrives; the last one finalizes.
    __threadfence();
    if (tid == 0) {
        const unsigned old = atomicAdd(&g_count, 1u);
        if (old == (unsigned)(gridDim.x - 1)) {
            const unsigned long long p = g_pairs;
            const double l = g_loss;
            out[0] = (float)((p > 0ull) ? (l / (double)p) : l);
            g_loss = 0.0;          // reset for next graph replay
            g_pairs = 0ull;
            g_count = 0u;
            __threadfence();
        }
    }
}

// ---------------------------------------------------------------------------
// Inputs: 0 f1 f32[256,1024]  1 f2 f32[256,1024]  2 mask_cross i32[256,256]
//         3 mask1 i32[256,256] 4 mask2 i32[256,256] 5/6 mask_sents bool[256]
// ---------------------------------------------------------------------------
extern "C" void kernel_launch(void* const* d_in, const int* in_sizes, int n_in,
                              void* d_out, int out_size) {
    const float* f1 = (const float*)d_in[0];
    const float* f2 = (const float*)d_in[1];
    const int* mc = (const int*)d_in[2];
    const int* m1 = (const int*)d_in[3];
    const int* m2 = (const int*)d_in[4];
    const unsigned char* s1 = (const unsigned char*)d_in[5];
    const unsigned char* s2 = (const unsigned char*)d_in[6];

    gemm_mma_kernel<<<192, 256>>>(f1, f2, s1, s2);
    loss_kernel<<<1024, 256>>>(mc, m1, m2, (const void*)s1, (const void*)s2,
                               (float*)d_out);
}

// round 13
// speedup vs baseline: 1.3282x; 1.0102x over previous
#include <cuda_runtime.h>
#include <cuda_bf16.h>
#include <cstdint>

namespace {
constexpr int NTOK = 256;
constexpr int DIM  = 1024;
}

// ---------------- scratch (static device globals, graph/alloc-safe) --------
__device__ float g_part[24][NTOK * NTOK];     // split-k partials: z = m*8 + s
__device__ double g_loss;                      // zero-init; reset by last loss block
__device__ unsigned long long g_pairs;         // idem
__device__ unsigned g_count;                   // idem
__device__ int g_selIsByte;

// ---------------- helpers ---------------------------------------------------
__device__ __forceinline__ uint32_t smem_u32(const void* p) {
    uint32_t a;
    asm("{ .reg .u64 t; cvta.to.shared.u64 t, %1; cvt.u32.u64 %0, t; }" : "=r"(a) : "l"(p));
    return a;
}
__device__ __forceinline__ void ldsm4(uint32_t* r, uint32_t addr) {
    asm volatile("ldmatrix.sync.aligned.m8n8.x4.shared.b16 {%0,%1,%2,%3}, [%4];"
                 : "=r"(r[0]), "=r"(r[1]), "=r"(r[2]), "=r"(r[3]) : "r"(addr));
}
__device__ __forceinline__ void mma_bf16(float* c, const uint32_t* a, const uint32_t* b) {
    asm volatile("mma.sync.aligned.m16n8k16.row.col.f32.bf16.bf16.f32 "
                 "{%0,%1,%2,%3}, {%4,%5,%6,%7}, {%8,%9}, {%0,%1,%2,%3};"
                 : "+f"(c[0]), "+f"(c[1]), "+f"(c[2]), "+f"(c[3])
                 : "r"(a[0]), "r"(a[1]), "r"(a[2]), "r"(a[3]), "r"(b[0]), "r"(b[1]));
}
// float4 -> packed hi bf16x4 (uint2) and lo bf16x4 (uint2)
__device__ __forceinline__ void split4(const float4 v, uint2& hi, uint2& lo) {
    __nv_bfloat16 h0 = __float2bfloat16_rn(v.x);
    __nv_bfloat16 h1 = __float2bfloat16_rn(v.y);
    __nv_bfloat16 h2 = __float2bfloat16_rn(v.z);
    __nv_bfloat16 h3 = __float2bfloat16_rn(v.w);
    __nv_bfloat162 hA(h0, h1), hB(h2, h3);
    __nv_bfloat162 lA(__float2bfloat16_rn(v.x - __bfloat162float(h0)),
                      __float2bfloat16_rn(v.y - __bfloat162float(h1)));
    __nv_bfloat162 lB(__float2bfloat16_rn(v.z - __bfloat162float(h2)),
                      __float2bfloat16_rn(v.w - __bfloat162float(h3)));
    hi = make_uint2(*(uint32_t*)&hA, *(uint32_t*)&hB);
    lo = make_uint2(*(uint32_t*)&lA, *(uint32_t*)&lB);
}

// ---------------------------------------------------------------------------
// Tensor GEMM with fused fp32 -> bf16 hi/lo conversion in the staging path.
// (unchanged from R12; see comments there)
// ---------------------------------------------------------------------------
__global__ __launch_bounds__(256) void gemm_mma_kernel(const float* __restrict__ f1,
                                                       const float* __restrict__ f2,
                                                       const unsigned char* __restrict__ s1,
                                                       const unsigned char* __restrict__ s2) {
    __shared__ __align__(16) __nv_bfloat16 sAh[128 * 72];
    __shared__ __align__(16) __nv_bfloat16 sAl[128 * 72];
    __shared__ __align__(16) __nv_bfloat16 sBh[64 * 72];
    __shared__ __align__(16) __nv_bfloat16 sBl[64 * 72];

    const int tid = threadIdx.x;
    const int lane = tid & 31;
    const int wid = tid >> 5;

    if (blockIdx.x == 0) {
        // mask_sents dtype sniff: int32 {0,1} has all non-word-aligned bytes 0
        int v = 0;
        if ((tid & 3) != 0) v = (int)s1[tid] | (int)s2[tid];
        const int any = __syncthreads_or(v);
        if (tid == 0) g_selIsByte = (any != 0) ? 1 : 0;
    }

    const int bz = blockIdx.x;
    const int tile = bz & 7;
    const int rt = tile >> 2;
    const int ct = tile & 3;
    const int zz = bz >> 3;
    const int m = zz >> 3;
    const int s = zz & 7;
    const int rbase = rt * 128;
    const int cbase = ct * 64;
    const int k0 = s * 128;

    const float* __restrict__ A = (m == 2) ? f2 : f1;
    const float* __restrict__ B = (m == 1) ? f1 : f2;

    const uint32_t uAh = smem_u32(sAh);
    const uint32_t uAl = smem_u32(sAl);
    const uint32_t uBh = smem_u32(sBh);
    const uint32_t uBl = smem_u32(sBl);

    const int wr = wid >> 1;
    const int wc = wid & 1;
    const int arow = lane & 15;
    const int acol = (lane >> 4) << 3;
    const uint32_t aoff = (uint32_t)(((wr * 32 + arow) * 72 + acol) * 2);
    const int bi = lane & 7;
    const int bq = lane >> 3;
    const uint32_t boff = (uint32_t)(((wc * 32 + ((bq >> 1) << 3) + bi) * 72 + ((bq & 1) << 3)) * 2);

    float C[2][4][4];
#pragma unroll
    for (int mt = 0; mt < 2; mt++)
#pragma unroll
        for (int nt = 0; nt < 4; nt++)
#pragma unroll
            for (int q = 0; q < 4; q++) C[mt][nt][q] = 0.f;

#pragma unroll
    for (int chunk = 0; chunk < 2; chunk++) {
        const int kg = k0 + chunk * 64;
        __syncthreads();
#pragma unroll
        for (int it = 0; it < 4; it++) {
            const int v = tid + it * 256;
            const int r = v >> 3;
            const int q = v & 7;
            const float* gp = &A[(rbase + r) * DIM + kg + q * 8];
            const float4 vx = *(const float4*)gp;
            const float4 vy = *(const float4*)(gp + 4);
            uint2 hx, lx, hy, ly;
            split4(vx, hx, lx);
            split4(vy, hy, ly);
            const int o = r * 72 + q * 8;
            *(uint4*)&sAh[o] = make_uint4(hx.x, hx.y, hy.x, hy.y);
            *(uint4*)&sAl[o] = make_uint4(lx.x, lx.y, ly.x, ly.y);
        }
#pragma unroll
        for (int it = 0; it < 2; it++) {
            const int v = tid + it * 256;
            const int r = v >> 3;
            const int q = v & 7;
            const float* gp = &B[(cbase + r) * DIM + kg + q * 8];
            const float4 vx = *(const float4*)gp;
            const float4 vy = *(const float4*)(gp + 4);
            uint2 hx, lx, hy, ly;
            split4(vx, hx, lx);
            split4(vy, hy, ly);
            const int o = r * 72 + q * 8;
            *(uint4*)&sBh[o] = make_uint4(hx.x, hx.y, hy.x, hy.y);
            *(uint4*)&sBl[o] = make_uint4(lx.x, lx.y, ly.x, ly.y);
        }
        __syncthreads();

#pragma unroll
        for (int kk = 0; kk < 4; kk++) {
            const uint32_t ka = aoff + kk * 32;
            const uint32_t kb = boff + kk * 32;
            uint32_t ah[2][4], al[2][4], bh[8], bl[8];
            ldsm4(ah[0], uAh + ka);
            ldsm4(ah[1], uAh + ka + 16 * 72 * 2);
            ldsm4(al[0], uAl + ka);
            ldsm4(al[1], uAl + ka + 16 * 72 * 2);
            ldsm4(bh,     uBh + kb);
            ldsm4(bh + 4, uBh + kb + 16 * 72 * 2);
            ldsm4(bl,     uBl + kb);
            ldsm4(bl + 4, uBl + kb + 16 * 72 * 2);
#pragma unroll
            for (int mt = 0; mt < 2; mt++)
#pragma unroll
                for (int nt = 0; nt < 4; nt++) {
                    mma_bf16(C[mt][nt], ah[mt], &bh[nt * 2]);
                    mma_bf16(C[mt][nt], ah[mt], &bl[nt * 2]);
                    mma_bf16(C[mt][nt], al[mt], &bh[nt * 2]);
                }
        }
    }

    float* __restrict__ dst = g_part[m * 8 + s];
    const int erow = lane >> 2;
    const int ecol = (lane & 3) * 2;
#pragma unroll
    for (int mt = 0; mt < 2; mt++)
#pragma unroll
        for (int nt = 0; nt < 4; nt++) {
            const int r0 = rbase + wr * 32 + mt * 16 + erow;
            const int cc = cbase + wc * 32 + nt * 8 + ecol;
            *(float2*)&dst[r0 * NTOK + cc] = make_float2(C[mt][nt][0], C[mt][nt][1]);
            *(float2*)&dst[(r0 + 8) * NTOK + cc] = make_float2(C[mt][nt][2], C[mt][nt][3]);
        }
}

// ---------------------------------------------------------------------------
// Loss inner loop. MUFU-diet version:
//  - EX2 executed ONLY when |x| < 10 (predicated asm; a C++ `if` would emit
//    BSSY/BSYNC and `?:` would still execute the MUFU). For |x|>=10,
//    log1p(e^-|x|) < 4.6e-5; x ~ N(0, 45^2), so ~82% of pairs skip; total
//    truncation <= ~3e-6 relative. Sentinel pairs (|x|~1e30) auto-skip.
//  - One LG2 per j-step: log(prodA*prodB) (each prod <= 2^4, product <= 256).
// ---------------------------------------------------------------------------
template <int NB>
__device__ __forceinline__ float row_loss(const float* __restrict__ sPos,
                                          const float* __restrict__ sNeg,
                                          int Ppad, int kl, int jg) {
    float nr[NB];
#pragma unroll
    for (int u = 0; u < NB; u++) nr[u] = sNeg[kl + u * 32];
    float relu = 0.f, lacc = 0.f;
    const float thr = -14.42695f;   // -10 * log2(e)
    for (int j = jg; j < Ppad; j += 8) {
        const float p = sPos[j];
        float prodA = 1.f, prodB = 1.f;
#pragma unroll
        for (int u = 0; u < NB; u++) {
            const float x = nr[u] - p;
            relu += fmaxf(x, 0.f);
            const float mx = fabsf(x) * (-1.442695041f);  // log2(e^-|x|)
            float* pr = (u & 1) ? &prodB : &prodA;
            asm volatile(
                "{\n\t"
                ".reg .pred q;\n\t"
                ".reg .f32 e;\n\t"
                "setp.gt.f32 q, %1, %2;\n\t"
                "@q ex2.approx.ftz.f32 e, %1;\n\t"
                "@q fma.rn.f32 %0, %0, e, %0;\n\t"
                "}" : "+f"(*pr) : "f"(mx), "f"(thr));
        }
        lacc += __logf(prodA * prodB);
    }
    return relu + lacc;
}

__global__ __launch_bounds__(256) void loss_kernel(const int* __restrict__ mc,
                                                   const int* __restrict__ m1,
                                                   const int* __restrict__ m2,
                                                   const void* __restrict__ s1p,
                                                   const void* __restrict__ s2p,
                                                   float* __restrict__ out) {
    const int r = blockIdx.x;
    const int t = r >> 8;
    const int i = r & 255;

    const void* selP = (t == 0 || t == 2) ? s1p : s2p;
    int sel;
    if (g_selIsByte) sel = ((const unsigned char*)selP)[i];
    else             sel = ((const int*)selP)[i];

    __shared__ float sPos[256];
    __shared__ float sNeg[256];
    __shared__ int wPos[8];
    __shared__ float sRed[8];

    const int tid = threadIdx.x;
    const int lane = tid & 31;
    const int wid = tid >> 5;

    if (sel) {  // uniform across block
        // fused split-k reduce while loading
        const int mIdx = (t <= 1) ? 0 : (t - 1);
        const int off = (t == 1) ? (tid * 256 + i) : (i * 256 + tid);
        const float* __restrict__ pb = g_part[mIdx * 8];
        float v = 0.f;
#pragma unroll
        for (int sp = 0; sp < 8; sp++) v += pb[sp * 65536 + off];

        int mk;
        if (t == 0)      mk = mc[i * 256 + tid];
        else if (t == 1) mk = mc[tid * 256 + i];
        else if (t == 2) mk = m1[i * 256 + tid];
        else             mk = m2[i * 256 + tid];

        const unsigned bp = __ballot_sync(0xffffffffu, mk != 0);
        if (lane == 0) wPos[wid] = __popc(bp);
        __syncthreads();

        int baseP = 0, P = 0;
#pragma unroll
        for (int w = 0; w < 8; w++) {
            const int c = wPos[w];
            if (w < wid) baseP += c;
            P += c;
        }
        const int N = 256 - P;
        const int baseN = wid * 32 - baseP;
        const unsigned lt = (1u << lane) - 1u;
        if (mk) sPos[baseP + __popc(bp & lt)] = v;
        else    sNeg[baseN + __popc(~bp & lt)] = v;
        __syncthreads();

        if (tid == 0)
            atomicAdd(&g_pairs, (unsigned long long)P * (unsigned long long)N);

        if (P != 0 && N != 0) {  // uniform
            const int Ppad = (P + 31) & ~31;
            const int Npad = (N + 31) & ~31;
            if (tid >= P && tid < Ppad) sPos[tid] = 1e30f;
            if (tid >= N && tid < Npad) sNeg[tid] = -1e30f;
            __syncthreads();

            const int kl = tid & 31;
            const int jg = tid >> 5;
            float total;
            switch (Npad >> 5) {
                case 1: total = row_loss<1>(sPos, sNeg, Ppad, kl, jg); break;
                case 2: total = row_loss<2>(sPos, sNeg, Ppad, kl, jg); break;
                case 3: total = row_loss<3>(sPos, sNeg, Ppad, kl, jg); break;
                case 4: total = row_loss<4>(sPos, sNeg, Ppad, kl, jg); break;
                case 5: total = row_loss<5>(sPos, sNeg, Ppad, kl, jg); break;
                case 6: total = row_loss<6>(sPos, sNeg, Ppad, kl, jg); break;
                case 7: total = row_loss<7>(sPos, sNeg, Ppad, kl, jg); break;
                default: total = row_loss<8>(sPos, sNeg, Ppad, kl, jg); break;
            }

#pragma unroll
            for (int o = 16; o; o >>= 1) total += __shfl_xor_sync(0xffffffffu, total, o);
            if (lane == 0) sRed[wid] = total;
            __syncthreads();
            if (tid == 0) {
                float bs = 0.f;
#pragma unroll
                for (int w = 0; w < 8; w++) bs += sRed[w];
                atomicAdd(&g_loss, (double)bs);
            }
        }
    }

    // Completion protocol: every block arrives; the last one finalizes.
    __threadfence();
    if (tid == 0) {
        const unsigned old = atomicAdd(&g_count, 1u);
        if (old == (unsigned)(gridDim.x - 1)) {
            const unsigned long long p = g_pairs;
            const double l = g_loss;
            out[0] = (float)((p > 0ull) ? (l / (double)p) : l);
            g_loss = 0.0;          // reset for next graph replay
            g_pairs = 0ull;
            g_count = 0u;
            __threadfence();
        }
    }
}

// ---------------------------------------------------------------------------
// Inputs: 0 f1 f32[256,1024]  1 f2 f32[256,1024]  2 mask_cross i32[256,256]
//         3 mask1 i32[256,256] 4 mask2 i32[256,256] 5/6 mask_sents bool[256]
// ---------------------------------------------------------------------------
extern "C" void kernel_launch(void* const* d_in, const int* in_sizes, int n_in,
                              void* d_out, int out_size) {
    const float* f1 = (const float*)d_in[0];
    const float* f2 = (const float*)d_in[1];
    const int* mc = (const int*)d_in[2];
    const int* m1 = (const int*)d_in[3];
    const int* m2 = (const int*)d_in[4];
    const unsigned char* s1 = (const unsigned char*)d_in[5];
    const unsigned char* s2 = (const unsigned char*)d_in[6];

    gemm_mma_kernel<<<192, 256>>>(f1, f2, s1, s2);
    loss_kernel<<<1024, 256>>>(mc, m1, m2, (const void*)s1, (const void*)s2,
                               (float*)d_out);
}

// round 14
// speedup vs baseline: 1.3489x; 1.0156x over previous
#include <cuda_runtime.h>
#include <cuda_bf16.h>
#include <cstdint>

namespace {
constexpr int NTOK = 256;
constexpr int DIM  = 1024;
}

// ---------------- scratch (static device globals, graph/alloc-safe) --------
__device__ float g_part[24][NTOK * NTOK];     // split-k partials: z = m*8 + s
__device__ double g_loss;                      // zero-init; reset by last loss block
__device__ unsigned long long g_pairs;         // idem
__device__ unsigned g_count;                   // idem
__device__ int g_selIsByte;

// ---------------- helpers ---------------------------------------------------
__device__ __forceinline__ uint32_t smem_u32(const void* p) {
    uint32_t a;
    asm("{ .reg .u64 t; cvta.to.shared.u64 t, %1; cvt.u32.u64 %0, t; }" : "=r"(a) : "l"(p));
    return a;
}
__device__ __forceinline__ void ldsm4(uint32_t* r, uint32_t addr) {
    asm volatile("ldmatrix.sync.aligned.m8n8.x4.shared.b16 {%0,%1,%2,%3}, [%4];"
                 : "=r"(r[0]), "=r"(r[1]), "=r"(r[2]), "=r"(r[3]) : "r"(addr));
}
__device__ __forceinline__ void mma_bf16(float* c, const uint32_t* a, const uint32_t* b) {
    asm volatile("mma.sync.aligned.m16n8k16.row.col.f32.bf16.bf16.f32 "
                 "{%0,%1,%2,%3}, {%4,%5,%6,%7}, {%8,%9}, {%0,%1,%2,%3};"
                 : "+f"(c[0]), "+f"(c[1]), "+f"(c[2]), "+f"(c[3])
                 : "r"(a[0]), "r"(a[1]), "r"(a[2]), "r"(a[3]), "r"(b[0]), "r"(b[1]));
}
// float4 -> packed hi bf16x4 (uint2) and lo bf16x4 (uint2)
__device__ __forceinline__ void split4(const float4 v, uint2& hi, uint2& lo) {
    __nv_bfloat16 h0 = __float2bfloat16_rn(v.x);
    __nv_bfloat16 h1 = __float2bfloat16_rn(v.y);
    __nv_bfloat16 h2 = __float2bfloat16_rn(v.z);
    __nv_bfloat16 h3 = __float2bfloat16_rn(v.w);
    __nv_bfloat162 hA(h0, h1), hB(h2, h3);
    __nv_bfloat162 lA(__float2bfloat16_rn(v.x - __bfloat162float(h0)),
                      __float2bfloat16_rn(v.y - __bfloat162float(h1)));
    __nv_bfloat162 lB(__float2bfloat16_rn(v.z - __bfloat162float(h2)),
                      __float2bfloat16_rn(v.w - __bfloat162float(h3)));
    hi = make_uint2(*(uint32_t*)&hA, *(uint32_t*)&hB);
    lo = make_uint2(*(uint32_t*)&lA, *(uint32_t*)&lB);
}

// ---------------------------------------------------------------------------
// Tensor GEMM with fused fp32 -> bf16 hi/lo conversion in the staging path.
// (unchanged from R12; see comments there)
// ---------------------------------------------------------------------------
__global__ __launch_bounds__(256) void gemm_mma_kernel(const float* __restrict__ f1,
                                                       const float* __restrict__ f2,
                                                       const unsigned char* __restrict__ s1,
                                                       const unsigned char* __restrict__ s2) {
    __shared__ __align__(16) __nv_bfloat16 sAh[128 * 72];
    __shared__ __align__(16) __nv_bfloat16 sAl[128 * 72];
    __shared__ __align__(16) __nv_bfloat16 sBh[64 * 72];
    __shared__ __align__(16) __nv_bfloat16 sBl[64 * 72];

    const int tid = threadIdx.x;
    const int lane = tid & 31;
    const int wid = tid >> 5;

    if (blockIdx.x == 0) {
        // mask_sents dtype sniff: int32 {0,1} has all non-word-aligned bytes 0
        int v = 0;
        if ((tid & 3) != 0) v = (int)s1[tid] | (int)s2[tid];
        const int any = __syncthreads_or(v);
        if (tid == 0) g_selIsByte = (any != 0) ? 1 : 0;
    }

    const int bz = blockIdx.x;
    const int tile = bz & 7;
    const int rt = tile >> 2;
    const int ct = tile & 3;
    const int zz = bz >> 3;
    const int m = zz >> 3;
    const int s = zz & 7;
    const int rbase = rt * 128;
    const int cbase = ct * 64;
    const int k0 = s * 128;

    const float* __restrict__ A = (m == 2) ? f2 : f1;
    const float* __restrict__ B = (m == 1) ? f1 : f2;

    const uint32_t uAh = smem_u32(sAh);
    const uint32_t uAl = smem_u32(sAl);
    const uint32_t uBh = smem_u32(sBh);
    const uint32_t uBl = smem_u32(sBl);

    const int wr = wid >> 1;
    const int wc = wid & 1;
    const int arow = lane & 15;
    const int acol = (lane >> 4) << 3;
    const uint32_t aoff = (uint32_t)(((wr * 32 + arow) * 72 + acol) * 2);
    const int bi = lane & 7;
    const int bq = lane >> 3;
    const uint32_t boff = (uint32_t)(((wc * 32 + ((bq >> 1) << 3) + bi) * 72 + ((bq & 1) << 3)) * 2);

    float C[2][4][4];
#pragma unroll
    for (int mt = 0; mt < 2; mt++)
#pragma unroll
        for (int nt = 0; nt < 4; nt++)
#pragma unroll
            for (int q = 0; q < 4; q++) C[mt][nt][q] = 0.f;

#pragma unroll
    for (int chunk = 0; chunk < 2; chunk++) {
        const int kg = k0 + chunk * 64;
        __syncthreads();
#pragma unroll
        for (int it = 0; it < 4; it++) {
            const int v = tid + it * 256;
            const int r = v >> 3;
            const int q = v & 7;
            const float* gp = &A[(rbase + r) * DIM + kg + q * 8];
            const float4 vx = *(const float4*)gp;
            const float4 vy = *(const float4*)(gp + 4);
            uint2 hx, lx, hy, ly;
            split4(vx, hx, lx);
            split4(vy, hy, ly);
            const int o = r * 72 + q * 8;
            *(uint4*)&sAh[o] = make_uint4(hx.x, hx.y, hy.x, hy.y);
            *(uint4*)&sAl[o] = make_uint4(lx.x, lx.y, ly.x, ly.y);
        }
#pragma unroll
        for (int it = 0; it < 2; it++) {
            const int v = tid + it * 256;
            const int r = v >> 3;
            const int q = v & 7;
            const float* gp = &B[(cbase + r) * DIM + kg + q * 8];
            const float4 vx = *(const float4*)gp;
            const float4 vy = *(const float4*)(gp + 4);
            uint2 hx, lx, hy, ly;
            split4(vx, hx, lx);
            split4(vy, hy, ly);
            const int o = r * 72 + q * 8;
            *(uint4*)&sBh[o] = make_uint4(hx.x, hx.y, hy.x, hy.y);
            *(uint4*)&sBl[o] = make_uint4(lx.x, lx.y, ly.x, ly.y);
        }
        __syncthreads();

#pragma unroll
        for (int kk = 0; kk < 4; kk++) {
            const uint32_t ka = aoff + kk * 32;
            const uint32_t kb = boff + kk * 32;
            uint32_t ah[2][4], al[2][4], bh[8], bl[8];
            ldsm4(ah[0], uAh + ka);
            ldsm4(ah[1], uAh + ka + 16 * 72 * 2);
            ldsm4(al[0], uAl + ka);
            ldsm4(al[1], uAl + ka + 16 * 72 * 2);
            ldsm4(bh,     uBh + kb);
            ldsm4(bh + 4, uBh + kb + 16 * 72 * 2);
            ldsm4(bl,     uBl + kb);
            ldsm4(bl + 4, uBl + kb + 16 * 72 * 2);
#pragma unroll
            for (int mt = 0; mt < 2; mt++)
#pragma unroll
                for (int nt = 0; nt < 4; nt++) {
                    mma_bf16(C[mt][nt], ah[mt], &bh[nt * 2]);
                    mma_bf16(C[mt][nt], ah[mt], &bl[nt * 2]);
                    mma_bf16(C[mt][nt], al[mt], &bh[nt * 2]);
                }
        }
    }

    float* __restrict__ dst = g_part[m * 8 + s];
    const int erow = lane >> 2;
    const int ecol = (lane & 3) * 2;
#pragma unroll
    for (int mt = 0; mt < 2; mt++)
#pragma unroll
        for (int nt = 0; nt < 4; nt++) {
            const int r0 = rbase + wr * 32 + mt * 16 + erow;
            const int cc = cbase + wc * 32 + nt * 8 + ecol;
            *(float2*)&dst[r0 * NTOK + cc] = make_float2(C[mt][nt][0], C[mt][nt][1]);
            *(float2*)&dst[(r0 + 8) * NTOK + cc] = make_float2(C[mt][nt][2], C[mt][nt][3]);
        }
}

// ---------------------------------------------------------------------------
// Loss inner loop. MUFU-diet with register-friendly predication:
//  - EX2 executed ONLY when |x| < 10 (predicated asm; log1p(e^-|x|) < 4.6e-5
//    beyond that; truncation ~3e-6 rel total). Sentinels auto-skip.
//  - Accumulator passed by reference, selected by COMPILE-TIME unroll parity
//    (the R13 version selected via a runtime pointer, which blew registers
//    32 -> 80 and halved occupancy).
//  - One LG2 per j-step: log(prodA*prodB).
// ---------------------------------------------------------------------------
__device__ __forceinline__ void pexp_fma(float& pr, float mx) {
    asm("{\n\t"
        ".reg .pred q;\n\t"
        ".reg .f32 e;\n\t"
        "setp.gt.f32 q, %1, 0fC166D89E;\n\t"   // -14.42695 = -10*log2(e)
        "@q ex2.approx.ftz.f32 e, %1;\n\t"
        "@q fma.rn.f32 %0, %0, e, %0;\n\t"
        "}" : "+f"(pr) : "f"(mx));
}

template <int NB>
__device__ __forceinline__ float row_loss(const float* __restrict__ sPos,
                                          const float* __restrict__ sNeg,
                                          int Ppad, int kl, int jg) {
    float nr[NB];
#pragma unroll
    for (int u = 0; u < NB; u++) nr[u] = sNeg[kl + u * 32];
    float relu = 0.f, lacc = 0.f;
    for (int j = jg; j < Ppad; j += 8) {
        const float p = sPos[j];
        float prodA = 1.f, prodB = 1.f;
#pragma unroll
        for (int u = 0; u < NB; u++) {
            const float x = nr[u] - p;
            relu += fmaxf(x, 0.f);
            const float mx = fabsf(x) * (-1.442695041f);  // log2(e^-|x|)
            if (u & 1) pexp_fma(prodB, mx);
            else       pexp_fma(prodA, mx);
        }
        lacc += __logf(prodA * prodB);
    }
    return relu + lacc;
}

__global__ __launch_bounds__(256, 5) void loss_kernel(const int* __restrict__ mc,
                                                      const int* __restrict__ m1,
                                                      const int* __restrict__ m2,
                                                      const void* __restrict__ s1p,
                                                      const void* __restrict__ s2p,
                                                      float* __restrict__ out) {
    const int r = blockIdx.x;
    const int t = r >> 8;
    const int i = r & 255;

    const void* selP = (t == 0 || t == 2) ? s1p : s2p;
    int sel;
    if (g_selIsByte) sel = ((const unsigned char*)selP)[i];
    else             sel = ((const int*)selP)[i];

    __shared__ float sPos[256];
    __shared__ float sNeg[256];
    __shared__ int wPos[8];
    __shared__ float sRed[8];

    const int tid = threadIdx.x;
    const int lane = tid & 31;
    const int wid = tid >> 5;

    if (sel) {  // uniform across block
        // fused split-k reduce while loading
        const int mIdx = (t <= 1) ? 0 : (t - 1);
        const int off = (t == 1) ? (tid * 256 + i) : (i * 256 + tid);
        const float* __restrict__ pb = g_part[mIdx * 8];
        float v = 0.f;
#pragma unroll
        for (int sp = 0; sp < 8; sp++) v += pb[sp * 65536 + off];

        int mk;
        if (t == 0)      mk = mc[i * 256 + tid];
        else if (t == 1) mk = mc[tid * 256 + i];
        else if (t == 2) mk = m1[i * 256 + tid];
        else             mk = m2[i * 256 + tid];

        const unsigned bp = __ballot_sync(0xffffffffu, mk != 0);
        if (lane == 0) wPos[wid] = __popc(bp);
        __syncthreads();

        int baseP = 0, P = 0;
#pragma unroll
        for (int w = 0; w < 8; w++) {
            const int c = wPos[w];
            if (w < wid) baseP += c;
            P += c;
        }
        const int N = 256 - P;
        const int baseN = wid * 32 - baseP;
        const unsigned lt = (1u << lane) - 1u;
        if (mk) sPos[baseP + __popc(bp & lt)] = v;
        else    sNeg[baseN + __popc(~bp & lt)] = v;
        __syncthreads();

        if (tid == 0)
            atomicAdd(&g_pairs, (unsigned long long)P * (unsigned long long)N);

        if (P != 0 && N != 0) {  // uniform
            const int Ppad = (P + 31) & ~31;
            const int Npad = (N + 31) & ~31;
            if (tid >= P && tid < Ppad) sPos[tid] = 1e30f;
            if (tid >= N && tid < Npad) sNeg[tid] = -1e30f;
            __syncthreads();

            const int kl = tid & 31;
            const int jg = tid >> 5;
            float total;
            switch (Npad >> 5) {
                case 1: total = row_loss<1>(sPos, sNeg, Ppad, kl, jg); break;
                case 2: total = row_loss<2>(sPos, sNeg, Ppad, kl, jg); break;
                case 3: total = row_loss<3>(sPos, sNeg, Ppad, kl, jg); break;
                case 4: total = row_loss<4>(sPos, sNeg, Ppad, kl, jg); break;
                case 5: total = row_loss<5>(sPos, sNeg, Ppad, kl, jg); break;
                case 6: total = row_loss<6>(sPos, sNeg, Ppad, kl, jg); break;
                case 7: total = row_loss<7>(sPos, sNeg, Ppad, kl, jg); break;
                default: total = row_loss<8>(sPos, sNeg, Ppad, kl, jg); break;
            }

#pragma unroll
            for (int o = 16; o; o >>= 1) total += __shfl_xor_sync(0xffffffffu, total, o);
            if (lane == 0) sRed[wid] = total;
            __syncthreads();
            if (tid == 0) {
                float bs = 0.f;
#pragma unroll
                for (int w = 0; w < 8; w++) bs += sRed[w];
                atomicAdd(&g_loss, (double)bs);
            }
        }
    }

    // Completion protocol: every block arrives; the last one finalizes.
    __threadfence();
    if (tid == 0) {
        const unsigned old = atomicAdd(&g_count, 1u);
        if (old == (unsigned)(gridDim.x - 1)) {
            const unsigned long long p = g_pairs;
            const double l = g_loss;
            out[0] = (float)((p > 0ull) ? (l / (double)p) : l);
            g_loss = 0.0;          // reset for next graph replay
            g_pairs = 0ull;
            g_count = 0u;
            __threadfence();
        }
    }
}

// ---------------------------------------------------------------------------
// Inputs: 0 f1 f32[256,1024]  1 f2 f32[256,1024]  2 mask_cross i32[256,256]
//         3 mask1 i32[256,256] 4 mask2 i32[256,256] 5/6 mask_sents bool[256]
// ---------------------------------------------------------------------------
extern "C" void kernel_launch(void* const* d_in, const int* in_sizes, int n_in,
                              void* d_out, int out_size) {
    const float* f1 = (const float*)d_in[0];
    const float* f2 = (const float*)d_in[1];
    const int* mc = (const int*)d_in[2];
    const int* m1 = (const int*)d_in[3];
    const int* m2 = (const int*)d_in[4];
    const unsigned char* s1 = (const unsigned char*)d_in[5];
    const unsigned char* s2 = (const unsigned char*)d_in[6];

    gemm_mma_kernel<<<192, 256>>>(f1, f2, s1, s2);
    loss_kernel<<<1024, 256>>>(mc, m1, m2, (const void*)s1, (const void*)s2,
                               (float*)d_out);
}